// round 16
// baseline (speedup 1.0000x reference)
#include <cuda_runtime.h>
#include <cuda_bf16.h>
#include <cstdint>

// Gridworld env step: warp-per-8-envs, software-pipelined cp.async gathers.
// Phase-locking breaker: scalars for all 8 envs fetched in ONE parallel round
// (shuffle-extracted), window gathers are fire-and-forget cp.async into a
// 3-deep smem ring, pipeline wait(1)/issue(i+2)/emit(i) hides gather latency
// behind the emit of previous envs.
//
// Inputs (metadata order):
//   0 grids (N,64,64) f32 | 1 energy (N,) f32 | 2 lut (5,) f32
//   3 agent_x (N,) i32 | 4 agent_y (N,) i32 | 5 agent_steps (unused)
//   6 actions (N,) i32 | 7 action_deltas (9,2) i32
// Output: obs (N, 6, 11, 11) f32

#define HW   64
#define VIEW 11
#define RAD  5
#define CELLS 121
#define OBS_PER_ENV 726
#define WARPS 4          // warps per block
#define EPW   8          // envs per warp
#define NBUF  3          // gather ring depth

__device__ __forceinline__ unsigned smem_u32(const void* p) {
    unsigned a;
    asm("{ .reg .u64 t; cvta.to.shared.u64 t, %1; cvt.u32.u64 %0, t; }"
        : "=r"(a) : "l"(p));
    return a;
}
__device__ __forceinline__ void cp16(unsigned saddr, const void* gaddr) {
    asm volatile("cp.async.cg.shared.global [%0], [%1], 16;"
                 :: "r"(saddr), "l"(gaddr) : "memory");
}
__device__ __forceinline__ void cp_commit() {
    asm volatile("cp.async.commit_group;" ::: "memory");
}
template <int N>
__device__ __forceinline__ void cp_wait() {
    asm volatile("cp.async.wait_group %0;" :: "n"(N) : "memory");
}

__global__ __launch_bounds__(128)
void env_step_kernel(const float* __restrict__ grids,
                     const float* __restrict__ energy_in,
                     const float* __restrict__ lut,
                     const int*   __restrict__ agent_x,
                     const int*   __restrict__ agent_y,
                     const int*   __restrict__ actions,
                     const int*   __restrict__ deltas,
                     float*       __restrict__ out,
                     int n_envs)
{
    __shared__ float  s_win[WARPS][NBUF][12][16];
    __shared__ float4 s_tab[4];

    const int wib  = threadIdx.x >> 5;
    const int lane = threadIdx.x & 31;
    const int env0 = (blockIdx.x * WARPS + wib) * EPW;

    // channel table: tab[v] = {v==2, v==3, v==1, lut[v]}
    if (threadIdx.x < 4) {
        float4 t;
        t.x = (threadIdx.x == 2) ? 1.0f : 0.0f;
        t.y = (threadIdx.x == 3) ? 1.0f : 0.0f;
        t.z = (threadIdx.x == 1) ? 1.0f : 0.0f;
        t.w = __ldg(lut + threadIdx.x);
        s_tab[threadIdx.x] = t;
    }
    __syncthreads();

    // ---- ONE parallel scalar round for all 8 envs ----
    int sv = 0;
    {
        const int le = env0 + (lane & 7);
        if (le < n_envs) {
            if      (lane <  8) sv = __ldg(actions + le);
            else if (lane < 16) sv = __ldg(agent_y + le);
            else if (lane < 24) sv = __ldg(agent_x + le);
            else                sv = __float_as_int(__ldg(energy_in + le));
        }
    }
    const int dval = (lane < 18) ? __ldg(deltas + lane) : 0;

    // per-env carried state (issue -> emit), kept in unrolled registers
    int   st_nyc[EPW], st_nxc[EPW], st_y[EPW], st_x[EPW], st_by[EPW], st_cb[EPW];
    float st_en[EPW];

    // gather task mapping: task t -> row t>>2 (0..11), 16B seg t&3
    const int r0 = lane >> 2,        s0 = lane & 3;          // tasks 0..31
    const int r1 = 8 + (lane >> 2),  s1 = lane & 3;          // tasks 32..47 (lane<16)

    auto issue_gather = [&](int e) {
        // derive this env's move candidate from the shared scalar round
        const int   a  = __shfl_sync(0xffffffffu, sv, e);
        const int   yy = __shfl_sync(0xffffffffu, sv, 8 + e);
        const int   xx = __shfl_sync(0xffffffffu, sv, 16 + e);
        const float en = __int_as_float(__shfl_sync(0xffffffffu, sv, 24 + e));
        const int   dy = __shfl_sync(0xffffffffu, dval, 2 * a);
        const int   dx = __shfl_sync(0xffffffffu, dval, 2 * a + 1);

        const int nyc = min(max(yy + dy, 0), HW - 1);
        const int nxc = min(max(xx + dx, 0), HW - 1);
        const int by  = min(yy, nyc) - RAD;
        const int cb  = min(max(min(xx, nxc) - RAD, 0) & ~3, HW - 16);

        st_nyc[e] = nyc; st_nxc[e] = nxc; st_y[e] = yy; st_x[e] = xx;
        st_by[e] = by;   st_cb[e] = cb;   st_en[e] = en;

        if (env0 + e < n_envs) {
            const float* __restrict__ g = grids + (size_t)(env0 + e) * (HW * HW);
            float (* __restrict__ w)[16] = s_win[wib][e % NBUF];
            // OOB rows: clamp — contents never read (emit bounds-checks)
            const int gy0 = min(max(by + r0, 0), HW - 1);
            cp16(smem_u32(&w[r0][4 * s0]), g + gy0 * HW + cb + 4 * s0);
            if (lane < 16) {
                const int gy1 = min(max(by + r1, 0), HW - 1);
                cp16(smem_u32(&w[r1][4 * s1]), g + gy1 * HW + cb + 4 * s1);
            }
        }
        cp_commit();        // unconditional: keeps group numbering aligned
    };

    // ---- prologue: 2 gathers in flight ----
    issue_gather(0);
    issue_gather(1);

    // ---- steady-state pipeline ----
    #pragma unroll
    for (int i = 0; i < EPW; i++) {
        cp_wait<1>();                   // gather(i) complete
        __syncwarp();

        if (i + 2 < EPW) issue_gather(i + 2);
        else             cp_commit();   // empty group, keep counts aligned

        if (env0 + i < n_envs) {
            const int by = st_by[i], cb = st_cb[i];
            float (* __restrict__ win)[16] = s_win[wib][i % NBUF];

            const float tgt   = win[st_nyc[i] - by][st_nxc[i] - cb];
            const float stayc = win[st_y[i]   - by][st_x[i]   - cb];

            const bool  blocked  = (tgt == 1.0f);
            const int   ny = blocked ? st_y[i] : st_nyc[i];
            const int   nx = blocked ? st_x[i] : st_nxc[i];
            const float cell     = blocked ? stayc : tgt;
            const bool  food     = (cell == 2.0f);
            const bool  poison   = (cell == 3.0f);
            const bool  consumed = food | poison;
            const float reward   = (food ? 10.0f : 0.0f) - (poison ? 10.0f : 0.0f);
            const float energy   = st_en[i] - 1.0f + reward;

            float* __restrict__ o = out + (size_t)(env0 + i) * OBS_PER_ENV;
            #pragma unroll
            for (int j = 0; j < 4; j++) {
                const int c = lane + 32 * j;
                if (c < CELLS) {
                    const int wy = c / VIEW - RAD;
                    const int wx = c % VIEW - RAD;
                    const int gy = ny + wy;
                    const int gx = nx + wx;
                    float v = 1.0f;                           // WALL padding
                    if ((unsigned)gy < (unsigned)HW && (unsigned)gx < (unsigned)HW)
                        v = win[gy - by][gx - cb];
                    if (consumed && c == 60) v = 0.0f;        // landed -> EMPTY
                    const float4 t = s_tab[(int)v];
                    float* oc = o + c;
                    oc[0 * CELLS] = t.x;
                    oc[1 * CELLS] = t.y;
                    oc[2 * CELLS] = t.z;
                    oc[3 * CELLS] = t.w;
                    oc[4 * CELLS] = v;
                    oc[5 * CELLS] = energy;
                }
            }
        }
    }
}

extern "C" void kernel_launch(void* const* d_in, const int* in_sizes, int n_in,
                              void* d_out, int out_size)
{
    const float* grids   = (const float*)d_in[0];
    const float* energy  = (const float*)d_in[1];
    const float* lut     = (const float*)d_in[2];
    const int*   ax      = (const int*)  d_in[3];
    const int*   ay      = (const int*)  d_in[4];
    // d_in[5] agent_steps unused
    const int*   actions = (const int*)  d_in[6];
    const int*   deltas  = (const int*)  d_in[7];
    float*       out     = (float*)      d_out;

    const int n_envs = in_sizes[1];
    const int envs_per_block = WARPS * EPW;                 // 32
    const int blocks = (n_envs + envs_per_block - 1) / envs_per_block;

    env_step_kernel<<<blocks, WARPS * 32>>>(grids, energy, lut, ax, ay,
                                            actions, deltas, out, n_envs);
}

// round 17
// speedup vs baseline: 1.1210x; 1.1210x over previous
#include <cuda_runtime.h>
#include <cuda_bf16.h>
#include <cstdint>

// Gridworld env step: warp-per-env union-window gather + table emit (R14),
// with L2 evict_last cache hints on gathers and output stores.
// Steady-state working set (24MB output + ~8MB gather lines, identical every
// graph replay) fits L2 (126MB); default policy churns it out -> ~14MB DRAM
// traffic per replay at scattered-effective ~1.3TB/s == the observed 10.5us.
// evict_last pins the set in L2 so warm replays run at L2 speed.
//
// Inputs (metadata order):
//   0 grids (N,64,64) f32 | 1 energy (N,) f32 | 2 lut (5,) f32
//   3 agent_x (N,) i32 | 4 agent_y (N,) i32 | 5 agent_steps (unused)
//   6 actions (N,) i32 | 7 action_deltas (9,2) i32
// Output: obs (N, 6, 11, 11) f32

#define HW   64
#define VIEW 11
#define RAD  5
#define CELLS 121
#define OBS_PER_ENV 726
#define WPB 8               // warps (=envs) per block

__device__ __forceinline__ unsigned long long mkpol() {
    unsigned long long p;
    asm("createpolicy.fractional.L2::evict_last.b64 %0, 1.0;" : "=l"(p));
    return p;
}
__device__ __forceinline__ float4 ldg_pol(const float* a, unsigned long long p) {
    float4 v;
    asm volatile("ld.global.nc.L2::cache_hint.v4.f32 {%0,%1,%2,%3}, [%4], %5;"
                 : "=f"(v.x), "=f"(v.y), "=f"(v.z), "=f"(v.w)
                 : "l"(a), "l"(p));
    return v;
}
__device__ __forceinline__ void stg_pol(float* a, float v, unsigned long long p) {
    asm volatile("st.global.L2::cache_hint.f32 [%0], %1, %2;"
                 :: "l"(a), "f"(v), "l"(p) : "memory");
}

__global__ __launch_bounds__(256)
void env_step_kernel(const float* __restrict__ grids,
                     const float* __restrict__ energy_in,
                     const float* __restrict__ lut,
                     const int*   __restrict__ agent_x,
                     const int*   __restrict__ agent_y,
                     const int*   __restrict__ actions,
                     const int*   __restrict__ deltas,
                     float*       __restrict__ out,
                     int n_envs)
{
    __shared__ float  s_win[WPB][12][16];
    __shared__ float4 s_tab[WPB][4];       // per-warp channel table

    const int wib  = threadIdx.x >> 5;
    const int lane = threadIdx.x & 31;
    const int env  = blockIdx.x * WPB + wib;
    if (env >= n_envs) return;

    const unsigned long long pol = mkpol();

    float (* __restrict__ win)[16] = s_win[wib];
    const float* __restrict__ g = grids + (size_t)env * (HW * HW);

    // ---- ROUND 1: independent scalar loads ----
    const int   a    = __ldg(actions   + env);
    const int   y0   = __ldg(agent_y   + env);
    const int   x0   = __ldg(agent_x   + env);
    const float en0  = __ldg(energy_in + env);
    const int   dval = (lane < 18) ? __ldg(deltas + lane) : 0;

    // channel table: tab[v] = {v==2, v==3, v==1, lut[v]}
    if (lane < 4) {
        float4 t;
        t.x = (lane == 2) ? 1.0f : 0.0f;   // food
        t.y = (lane == 3) ? 1.0f : 0.0f;   // poison
        t.z = (lane == 1) ? 1.0f : 0.0f;   // wall
        t.w = __ldg(lut + lane);           // interestingness
        s_tab[wib][lane] = t;
    }

    const int dy = __shfl_sync(0xffffffffu, dval, 2 * a);
    const int dx = __shfl_sync(0xffffffffu, dval, 2 * a + 1);

    const int nyc = min(max(y0 + dy, 0), HW - 1);
    const int nxc = min(max(x0 + dx, 0), HW - 1);

    // union-window origin (covers both 11x11 windows; extent <= 12x12)
    const int by = min(y0, nyc) - RAD;
    const int bx = min(x0, nxc) - RAD;
    const int cb = min(max(bx, 0) & ~3, HW - 16);     // 16B-aligned col base

    // ---- ROUND 2: single gather — 48 float4 tasks into smem ----
    #pragma unroll
    for (int it = 0; it < 2; it++) {
        const int task = lane + 32 * it;
        if (task < 48) {
            const int r  = task >> 2;
            const int s  = task & 3;
            const int gy = by + r;
            if ((unsigned)gy < (unsigned)HW) {
                const float4 v = ldg_pol(g + gy * HW + cb + 4 * s, pol);
                *(float4*)&win[r][4 * s] = v;
            }
        }
    }
    __syncwarp();

    // ---- resolve move (broadcast LDS) ----
    const float tgt   = win[nyc - by][nxc - cb];
    const float stayc = win[y0  - by][x0  - cb];

    const bool  blocked  = (tgt == 1.0f);
    const int   ny = blocked ? y0 : nyc;
    const int   nx = blocked ? x0 : nxc;
    const float cell     = blocked ? stayc : tgt;
    const bool  food     = (cell == 2.0f);
    const bool  poison   = (cell == 3.0f);
    const bool  consumed = food | poison;
    const float reward   = (food ? 10.0f : 0.0f) - (poison ? 10.0f : 0.0f);
    const float energy   = en0 - 1.0f + reward;

    // bake consumed landed-cell into window: becomes EMPTY
    if (lane == 0)
        win[ny - by][nx - cb] = consumed ? 0.0f : cell;
    __syncwarp();

    // ---- emit: per cell = 1 LDS + F2I + 1 LDS.128 + 6 STG (evict_last) ----
    const float4* __restrict__ tab = s_tab[wib];
    float* __restrict__ o = out + (size_t)env * OBS_PER_ENV;
    #pragma unroll
    for (int j = 0; j < 4; j++) {
        const int c = lane + 32 * j;
        if (c < CELLS) {
            const int wy = c / VIEW - RAD;
            const int wx = c % VIEW - RAD;
            const int gy = ny + wy;
            const int gx = nx + wx;
            float v = 1.0f;                               // WALL padding
            if ((unsigned)gy < (unsigned)HW && (unsigned)gx < (unsigned)HW)
                v = win[gy - by][gx - cb];
            const float4 t = tab[(int)v];
            float* oc = o + c;
            stg_pol(oc + 0 * CELLS, t.x, pol);
            stg_pol(oc + 1 * CELLS, t.y, pol);
            stg_pol(oc + 2 * CELLS, t.z, pol);
            stg_pol(oc + 3 * CELLS, t.w, pol);
            stg_pol(oc + 4 * CELLS, v,   pol);
            stg_pol(oc + 5 * CELLS, energy, pol);
        }
    }
}

extern "C" void kernel_launch(void* const* d_in, const int* in_sizes, int n_in,
                              void* d_out, int out_size)
{
    const float* grids   = (const float*)d_in[0];
    const float* energy  = (const float*)d_in[1];
    const float* lut     = (const float*)d_in[2];
    const int*   ax      = (const int*)  d_in[3];
    const int*   ay      = (const int*)  d_in[4];
    // d_in[5] agent_steps unused
    const int*   actions = (const int*)  d_in[6];
    const int*   deltas  = (const int*)  d_in[7];
    float*       out     = (float*)      d_out;

    const int n_envs = in_sizes[1];
    const int blocks = (n_envs + WPB - 1) / WPB;

    env_step_kernel<<<blocks, 256>>>(grids, energy, lut, ax, ay, actions, deltas, out, n_envs);
}